// round 2
// baseline (speedup 1.0000x reference)
#include <cuda_runtime.h>
#include <cstdint>

#define FN   128
#define FE   32
#define MSGW 32
#define QW   192          // Q columns: [0,32)=nf@We0, [32,64)=nf@We1, [64,192)=nf@Wn0
#define MAXN 50000
#define MAXE 600000

__device__ float g_Q[(size_t)MAXN * QW];     // 38.4 MB
__device__ float g_MS[(size_t)MAXN * MSGW];  // 6.4 MB
__device__ int   g_n0[MAXE];
__device__ int   g_n1[MAXE];
__device__ int   g_is64;

// ---------------------------------------------------------------------------
// Detect index dtype: int64 indices (values < 50000) have zero high words.
// If the buffer is int32, odd words are random node ids -> almost surely
// nonzero among 16384 samples. Deterministic for fixed input.
// ---------------------------------------------------------------------------
__global__ void k_detect(const unsigned* __restrict__ wds, int E) {
    __shared__ unsigned red[128];
    int sample = min(16384, E);
    unsigned v = 0;
    for (int i = threadIdx.x; i < sample; i += 128)
        v |= wds[2 * i + 1];
    red[threadIdx.x] = v;
    __syncthreads();
    for (int s = 64; s > 0; s >>= 1) {
        if (threadIdx.x < s) red[threadIdx.x] |= red[threadIdx.x + s];
        __syncthreads();
    }
    if (threadIdx.x == 0) g_is64 = (red[0] == 0u) ? 1 : 0;
}

// ---------------------------------------------------------------------------
// Narrow indices to int32 arrays + zero message sums.
// ---------------------------------------------------------------------------
__global__ void k_prep(const void* __restrict__ idx, int E, int N) {
    int i      = blockIdx.x * blockDim.x + threadIdx.x;
    int stride = gridDim.x * blockDim.x;
    int is64   = g_is64;
    for (int e = i; e < E; e += stride) {
        if (is64) {
            const long long* p = (const long long*)idx;
            g_n0[e] = (int)p[e];
            g_n1[e] = (int)p[(size_t)E + e];
        } else {
            const int* p = (const int*)idx;
            g_n0[e] = p[e];
            g_n1[e] = p[(size_t)E + e];
        }
    }
    int tot = N * MSGW;
    for (int j = i; j < tot; j += stride) g_MS[j] = 0.0f;
}

// ---------------------------------------------------------------------------
// K1: Q[N,192] = nf[N,128] @ [We0 | We1 | Wn0]   (fused node GEMM)
// Tile: 64 rows x 192 cols, K-chunks of 32. 256 threads.
// Thread (rg=t/32, cg=t%32) owns rows rg*8..+7, cols cg*6..+5 (48 acc).
// ---------------------------------------------------------------------------
__global__ __launch_bounds__(256) void k_gemm1(const float* __restrict__ nf,
                                               const float* __restrict__ We,
                                               const float* __restrict__ Wn,
                                               int N) {
    __shared__ float sA[32 * 65];    // A^T chunk: sA[k][m], pad 65
    __shared__ float sW[32 * 192];   // fused W chunk

    int t  = threadIdx.x;
    int m0 = blockIdx.x * 64;
    int rg = t >> 5;
    int cg = t & 31;

    float acc[8][6];
#pragma unroll
    for (int r = 0; r < 8; r++)
#pragma unroll
        for (int c = 0; c < 6; c++) acc[r][c] = 0.0f;

    for (int kc = 0; kc < FN; kc += 32) {
        __syncthreads();
        // load A chunk transposed: 2048 elems
#pragma unroll
        for (int id = t; id < 64 * 32; id += 256) {
            int m = id >> 5, k = id & 31;
            int n = m0 + m;
            sA[k * 65 + m] = (n < N) ? nf[(size_t)n * FN + kc + k] : 0.0f;
        }
        // load fused W chunk: 6144 elems
#pragma unroll
        for (int id = t; id < 32 * 192; id += 256) {
            int k = id / 192, c = id - k * 192;
            float v;
            if (c < 32)      v = We[(size_t)(kc + k) * MSGW + c];
            else if (c < 64) v = We[(size_t)(FN + kc + k) * MSGW + (c - 32)];
            else             v = Wn[(size_t)(kc + k) * FN + (c - 64)];
            sW[k * 192 + c] = v;
        }
        __syncthreads();

#pragma unroll 4
        for (int kk = 0; kk < 32; kk++) {
            float a[8], w[6];
#pragma unroll
            for (int r = 0; r < 8; r++) a[r] = sA[kk * 65 + rg * 8 + r];
#pragma unroll
            for (int c = 0; c < 6; c++) w[c] = sW[kk * 192 + cg * 6 + c];
#pragma unroll
            for (int r = 0; r < 8; r++)
#pragma unroll
                for (int c = 0; c < 6; c++)
                    acc[r][c] = fmaf(a[r], w[c], acc[r][c]);
        }
    }

#pragma unroll
    for (int r = 0; r < 8; r++) {
        int n = m0 + rg * 8 + r;
        if (n < N) {
            float* q = &g_Q[(size_t)n * QW + cg * 6];
#pragma unroll
            for (int c = 0; c < 6; c++) q[c] = acc[r][c];
        }
    }
}

// ---------------------------------------------------------------------------
// K2: per-edge message + scatter.
// One warp per edge. msg = relu(Q[n0,0:32] + Q[n1,32:64] + ef@We2 + be)
// atomicAdd into g_MS[n0] (one coalesced 128B line per edge).
// ---------------------------------------------------------------------------
__global__ __launch_bounds__(256) void k_edges(const float* __restrict__ ef,
                                               const float* __restrict__ We,
                                               const float* __restrict__ be,
                                               int E) {
    __shared__ float sW2[32 * 33];
    int t = threadIdx.x;
#pragma unroll
    for (int id = t; id < 32 * 32; id += 256) {
        int k = id >> 5, j = id & 31;
        sW2[k * 33 + j] = We[(size_t)(2 * FN + k) * MSGW + j];
    }
    __syncthreads();

    int lane   = t & 31;
    float bev  = be[lane];
    int warp   = (blockIdx.x * blockDim.x + t) >> 5;
    int nwarps = (gridDim.x * blockDim.x) >> 5;

    for (int e = warp; e < E; e += nwarps) {
        int n0 = g_n0[e];
        int n1 = g_n1[e];
        float v = ef[(size_t)e * FE + lane];
        float acc = g_Q[(size_t)n0 * QW + lane]
                  + g_Q[(size_t)n1 * QW + 32 + lane] + bev;
#pragma unroll
        for (int k = 0; k < 32; k++) {
            float b = __shfl_sync(0xffffffffu, v, k);
            acc = fmaf(b, sW2[k * 33 + lane], acc);
        }
        acc = fmaxf(acc, 0.0f);
        atomicAdd(&g_MS[(size_t)n0 * MSGW + lane], acc);
    }
}

// ---------------------------------------------------------------------------
// K3: out[N,128] = relu(Q[:,64:192] + MS @ Wn1 + bn)
// One warp per node; lane owns cols {lane, lane+32, lane+64, lane+96}.
// ---------------------------------------------------------------------------
__global__ __launch_bounds__(256) void k_nodes(const float* __restrict__ Wn,
                                               const float* __restrict__ bn,
                                               float* __restrict__ out,
                                               int N) {
    __shared__ float sW[32 * 128];
    __shared__ float sBn[128];
    int t = threadIdx.x;
#pragma unroll
    for (int id = t; id < 32 * 128; id += 256) {
        int k = id >> 7, c = id & 127;
        sW[k * 128 + c] = Wn[(size_t)(FN + k) * FN + c];
    }
    if (t < 128) sBn[t] = bn[t];
    __syncthreads();

    int lane   = t & 31;
    int warp   = (blockIdx.x * blockDim.x + t) >> 5;
    int nwarps = (gridDim.x * blockDim.x) >> 5;

    for (int n = warp; n < N; n += nwarps) {
        float m = g_MS[(size_t)n * MSGW + lane];
        float acc[4];
#pragma unroll
        for (int c = 0; c < 4; c++)
            acc[c] = g_Q[(size_t)n * QW + 64 + lane + 32 * c];
#pragma unroll
        for (int k = 0; k < 32; k++) {
            float b = __shfl_sync(0xffffffffu, m, k);
#pragma unroll
            for (int c = 0; c < 4; c++)
                acc[c] = fmaf(b, sW[k * 128 + lane + 32 * c], acc[c]);
        }
#pragma unroll
        for (int c = 0; c < 4; c++)
            out[(size_t)n * FN + lane + 32 * c] =
                fmaxf(acc[c] + sBn[lane + 32 * c], 0.0f);
    }
}

// ---------------------------------------------------------------------------
extern "C" void kernel_launch(void* const* d_in, const int* in_sizes, int n_in,
                              void* d_out, int out_size) {
    const float* nf  = (const float*)d_in[0];
    const void*  idx = d_in[1];
    const float* ef  = (const float*)d_in[2];
    const float* We  = (const float*)d_in[3];
    const float* be  = (const float*)d_in[4];
    const float* Wn  = (const float*)d_in[5];
    const float* bn  = (const float*)d_in[6];
    float* out = (float*)d_out;

    int N = in_sizes[0] / FN;   // 50000
    int E = in_sizes[2] / FE;   // 600000 (from edge_features, dtype-unambiguous)

    k_detect<<<1, 128>>>((const unsigned*)idx, E);

    int prepBlocks = (E + 255) / 256;
    k_prep<<<prepBlocks, 256>>>(idx, E, N);

    k_gemm1<<<(N + 63) / 64, 256>>>(nf, We, Wn, N);

    k_edges<<<1184, 256>>>(ef, We, be, E);

    k_nodes<<<1184, 256>>>(Wn, bn, out, N);
}

// round 3
// speedup vs baseline: 1.0970x; 1.0970x over previous
#include <cuda_runtime.h>
#include <cstdint>

#define FN   128
#define FE   32
#define MSGW 32
#define QW   192          // Q cols: [0,32)=nf@We0, [32,64)=nf@We1, [64,192)=nf@Wn0
#define MAXN 50000
#define BE   128          // edges per block in k_edges

__device__ float g_Q[(size_t)MAXN * QW];     // 38.4 MB
__device__ float g_MS[(size_t)MAXN * MSGW];  // 6.4 MB
__device__ int   g_is64;

static __device__ __forceinline__ unsigned long long pack2(float lo, float hi) {
    unsigned long long r;
    asm("mov.b64 %0, {%1,%2};" : "=l"(r) : "f"(lo), "f"(hi));
    return r;
}
static __device__ __forceinline__ void unpack2(unsigned long long v, float& lo, float& hi) {
    asm("mov.b64 {%0,%1}, %2;" : "=f"(lo), "=f"(hi) : "l"(v));
}
#define FMA2(acc, a, b) asm("fma.rn.f32x2 %0, %1, %2, %0;" : "+l"(acc) : "l"(a), "l"(b))

// ---------------------------------------------------------------------------
// Detect index dtype: int64 indices (< 50000) have zero high words.
// ---------------------------------------------------------------------------
__global__ void k_detect(const unsigned* __restrict__ wds, int E) {
    __shared__ unsigned red[128];
    int sample = min(16384, E);
    unsigned v = 0;
    for (int i = threadIdx.x; i < sample; i += 128) v |= wds[2 * i + 1];
    red[threadIdx.x] = v;
    __syncthreads();
    for (int s = 64; s > 0; s >>= 1) {
        if (threadIdx.x < s) red[threadIdx.x] |= red[threadIdx.x + s];
        __syncthreads();
    }
    if (threadIdx.x == 0) g_is64 = (red[0] == 0u) ? 1 : 0;
}

// ---------------------------------------------------------------------------
// Zero message sums (float4 stores).
// ---------------------------------------------------------------------------
__global__ void k_zero(int N) {
    int i = blockIdx.x * blockDim.x + threadIdx.x;
    int tot4 = N * MSGW / 4;
    float4 z = make_float4(0.f, 0.f, 0.f, 0.f);
    if (i < tot4) ((float4*)g_MS)[i] = z;
}

// ---------------------------------------------------------------------------
// K1: Q[N,192] = nf[N,128] @ [We0 | We1 | Wn0], f32x2 packed along M.
// Tile 64 rows x 192 cols, K-chunks of 32, 256 threads.
// Thread (rg=t/32, cg=t%32): rows rg*8..+7 (4 packed pairs), cols cg*6..+5.
// ---------------------------------------------------------------------------
__global__ __launch_bounds__(256) void k_gemm1(const float* __restrict__ nf,
                                               const float* __restrict__ We,
                                               const float* __restrict__ Wn,
                                               int N) {
    __shared__ float sA[32 * 68];    // A^T chunk [k][m], pad 68 (16B-mult rows)
    __shared__ float sW[32 * 192];   // fused weight chunk [k][c]

    int t  = threadIdx.x;
    int m0 = blockIdx.x * 64;
    int rg = t >> 5;
    int cg = t & 31;

    unsigned long long acc2[4][6];
#pragma unroll
    for (int p = 0; p < 4; p++)
#pragma unroll
        for (int c = 0; c < 6; c++) acc2[p][c] = 0ULL;

    for (int kc = 0; kc < FN; kc += 32) {
        __syncthreads();
#pragma unroll
        for (int id = t; id < 64 * 32; id += 256) {
            int m = id >> 5, k = id & 31;
            int n = m0 + m;
            sA[k * 68 + m] = (n < N) ? nf[(size_t)n * FN + kc + k] : 0.f;
        }
#pragma unroll
        for (int id = t; id < 32 * 192; id += 256) {
            int k = id / 192, c = id - k * 192;
            float v;
            if (c < 32)      v = We[(size_t)(kc + k) * MSGW + c];
            else if (c < 64) v = We[(size_t)(FN + kc + k) * MSGW + (c - 32)];
            else             v = Wn[(size_t)(kc + k) * FN + (c - 64)];
            sW[k * 192 + c] = v;
        }
        __syncthreads();

#pragma unroll 2
        for (int kk = 0; kk < 32; kk++) {
            float4 a01 = *(const float4*)&sA[kk * 68 + rg * 8];
            float4 a23 = *(const float4*)&sA[kk * 68 + rg * 8 + 4];
            unsigned long long a[4] = {pack2(a01.x, a01.y), pack2(a01.z, a01.w),
                                       pack2(a23.x, a23.y), pack2(a23.z, a23.w)};
            const float2* wp = (const float2*)&sW[kk * 192 + cg * 6];
            float2 w01 = wp[0], w23 = wp[1], w45 = wp[2];
            unsigned long long w[6] = {pack2(w01.x, w01.x), pack2(w01.y, w01.y),
                                       pack2(w23.x, w23.x), pack2(w23.y, w23.y),
                                       pack2(w45.x, w45.x), pack2(w45.y, w45.y)};
#pragma unroll
            for (int p = 0; p < 4; p++)
#pragma unroll
                for (int c = 0; c < 6; c++) FMA2(acc2[p][c], a[p], w[c]);
        }
    }

#pragma unroll
    for (int p = 0; p < 4; p++) {
        int n_lo = m0 + rg * 8 + 2 * p;
#pragma unroll
        for (int c = 0; c < 6; c++) {
            float lo, hi;
            unpack2(acc2[p][c], lo, hi);
            if (n_lo < N)     g_Q[(size_t)n_lo * QW + cg * 6 + c]       = lo;
            if (n_lo + 1 < N) g_Q[(size_t)(n_lo + 1) * QW + cg * 6 + c] = hi;
        }
    }
}

// ---------------------------------------------------------------------------
// K2 fused: per-block 128 edges.
//  Phase A: stage ef tile + indices, compute msg_part = ef @ We2 (f32x2 GEMM).
//  Phase B: msg = relu(msg_part + Q[n0,0:32] + Q[n1,32:64] + be),
//           red.global.add.v4.f32 into g_MS[n0] (8 lanes/edge, float4).
// ---------------------------------------------------------------------------
__global__ __launch_bounds__(256) void k_edges(const void* __restrict__ idx,
                                               const float* __restrict__ ef,
                                               const float* __restrict__ We,
                                               const float* __restrict__ be,
                                               int E) {
    __shared__ float sA[32 * 132];   // ef^T [k][m]
    __shared__ float sM[BE * 36];    // msg [m][c], pad 36 (16B-mult rows)
    __shared__ int   sN0[BE], sN1[BE];
    __shared__ float sW2[32 * 33];   // We2 [k][c]
    __shared__ float sBe[32];

    int t  = threadIdx.x;
    int e0 = blockIdx.x * BE;

#pragma unroll
    for (int id = t; id < 32 * 32; id += 256) {
        int k = id >> 5, c = id & 31;
        sW2[k * 33 + c] = We[(size_t)(2 * FN + k) * MSGW + c];
    }
    if (t < 32) sBe[t] = be[t];
    if (t < BE) {
        int e = e0 + t;
        if (e < E) {
            if (g_is64) {
                const long long* p = (const long long*)idx;
                sN0[t] = (int)p[e];
                sN1[t] = (int)p[(size_t)E + e];
            } else {
                const int* p = (const int*)idx;
                sN0[t] = p[e];
                sN1[t] = p[(size_t)E + e];
            }
        } else {
            sN0[t] = -1;
            sN1[t] = 0;
        }
    }
#pragma unroll
    for (int id = t; id < BE * 32; id += 256) {
        int m = id >> 5, k = id & 31;
        int e = e0 + m;
        sA[k * 132 + m] = (e < E) ? ef[(size_t)e * FE + k] : 0.f;
    }
    __syncthreads();

    // --- Phase A: msg_part = ef @ We2 ---
    int row_g = t & 15;   // rows row_g*8..+7 (4 packed pairs)
    int col_g = t >> 4;   // cols col_g*2..+1
    unsigned long long acc2[4][2];
#pragma unroll
    for (int p = 0; p < 4; p++) { acc2[p][0] = 0ULL; acc2[p][1] = 0ULL; }

#pragma unroll 4
    for (int kk = 0; kk < 32; kk++) {
        float4 a01 = *(const float4*)&sA[kk * 132 + row_g * 8];
        float4 a23 = *(const float4*)&sA[kk * 132 + row_g * 8 + 4];
        unsigned long long a[4] = {pack2(a01.x, a01.y), pack2(a01.z, a01.w),
                                   pack2(a23.x, a23.y), pack2(a23.z, a23.w)};
        float w0 = sW2[kk * 33 + col_g * 2];
        float w1 = sW2[kk * 33 + col_g * 2 + 1];
        unsigned long long wp0 = pack2(w0, w0), wp1 = pack2(w1, w1);
#pragma unroll
        for (int p = 0; p < 4; p++) {
            FMA2(acc2[p][0], a[p], wp0);
            FMA2(acc2[p][1], a[p], wp1);
        }
    }
#pragma unroll
    for (int p = 0; p < 4; p++) {
        int m = row_g * 8 + 2 * p;
#pragma unroll
        for (int c = 0; c < 2; c++) {
            float lo, hi;
            unpack2(acc2[p][c], lo, hi);
            sM[m * 36 + col_g * 2 + c]       = lo;
            sM[(m + 1) * 36 + col_g * 2 + c] = hi;
        }
    }
    __syncthreads();

    // --- Phase B: gather + relu + vector scatter ---
    int sub = t & 7;   // 8 lanes per edge, cols sub*4..+3
#pragma unroll
    for (int pass = 0; pass < 4; pass++) {
        int m  = pass * 32 + (t >> 3);
        int n0 = sN0[m];
        if (n0 >= 0) {
            int n1 = sN1[m];
            float4 mv = *(const float4*)&sM[m * 36 + sub * 4];
            float4 q0 = *((const float4*)&g_Q[(size_t)n0 * QW] + sub);
            float4 q1 = *((const float4*)&g_Q[(size_t)n1 * QW + 32] + sub);
            float4 bv = *(const float4*)&sBe[sub * 4];
            float x0 = fmaxf(mv.x + q0.x + q1.x + bv.x, 0.f);
            float x1 = fmaxf(mv.y + q0.y + q1.y + bv.y, 0.f);
            float x2 = fmaxf(mv.z + q0.z + q1.z + bv.z, 0.f);
            float x3 = fmaxf(mv.w + q0.w + q1.w + bv.w, 0.f);
            float* dst = &g_MS[(size_t)n0 * MSGW + sub * 4];
            asm volatile("red.global.add.v4.f32 [%0], {%1,%2,%3,%4};"
                         :: "l"(dst), "f"(x0), "f"(x1), "f"(x2), "f"(x3)
                         : "memory");
        }
    }
}

// ---------------------------------------------------------------------------
// K3: out[N,128] = relu(Q[:,64:192] + MS @ Wn1 + bn). One warp per node.
// ---------------------------------------------------------------------------
__global__ __launch_bounds__(256) void k_nodes(const float* __restrict__ Wn,
                                               const float* __restrict__ bn,
                                               float* __restrict__ out,
                                               int N) {
    __shared__ float sW[32 * 128];
    __shared__ float sBn[128];
    int t = threadIdx.x;
#pragma unroll
    for (int id = t; id < 32 * 128; id += 256) {
        int k = id >> 7, c = id & 127;
        sW[k * 128 + c] = Wn[(size_t)(FN + k) * FN + c];
    }
    if (t < 128) sBn[t] = bn[t];
    __syncthreads();

    int lane   = t & 31;
    int warp   = (blockIdx.x * blockDim.x + t) >> 5;
    int nwarps = (gridDim.x * blockDim.x) >> 5;

    for (int n = warp; n < N; n += nwarps) {
        float m = g_MS[(size_t)n * MSGW + lane];
        float acc[4];
#pragma unroll
        for (int c = 0; c < 4; c++)
            acc[c] = g_Q[(size_t)n * QW + 64 + lane + 32 * c];
#pragma unroll
        for (int k = 0; k < 32; k++) {
            float b = __shfl_sync(0xffffffffu, m, k);
#pragma unroll
            for (int c = 0; c < 4; c++)
                acc[c] = fmaf(b, sW[k * 128 + lane + 32 * c], acc[c]);
        }
#pragma unroll
        for (int c = 0; c < 4; c++)
            out[(size_t)n * FN + lane + 32 * c] =
                fmaxf(acc[c] + sBn[lane + 32 * c], 0.f);
    }
}

// ---------------------------------------------------------------------------
extern "C" void kernel_launch(void* const* d_in, const int* in_sizes, int n_in,
                              void* d_out, int out_size) {
    const float* nf  = (const float*)d_in[0];
    const void*  idx = d_in[1];
    const float* ef  = (const float*)d_in[2];
    const float* We  = (const float*)d_in[3];
    const float* be  = (const float*)d_in[4];
    const float* Wn  = (const float*)d_in[5];
    const float* bn  = (const float*)d_in[6];
    float* out = (float*)d_out;

    int N = in_sizes[0] / FN;
    int E = in_sizes[2] / FE;

    k_detect<<<1, 128>>>((const unsigned*)idx, E);
    k_zero<<<(N * MSGW / 4 + 255) / 256, 256>>>(N);
    k_gemm1<<<(N + 63) / 64, 256>>>(nf, We, Wn, N);
    k_edges<<<(E + BE - 1) / BE, 256>>>(idx, ef, We, be, E);
    k_nodes<<<1184, 256>>>(Wn, bn, out, N);
}